// round 1
// baseline (speedup 1.0000x reference)
#include <cuda_runtime.h>
#include <math.h>

#define Nb   8
#define NRr  300
#define Dd   256
#define Hh   8
#define Ss   49
#define DDd  64
#define FFf  2048
#define NCc  80
#define MTOT (Nb*NRr)          // 2400
#define PAR  32768             // 2*D*DD

// ---------------- scratch (device globals; no allocation allowed) ----------------
__device__ float g_qk  [MTOT*Dd];
__device__ float g_qp  [MTOT*Dd];
__device__ float g_kp  [MTOT*Dd];
__device__ float g_vp  [MTOT*Dd];
__device__ float g_ctx [MTOT*Dd];
__device__ float g_t   [MTOT*Dd];
__device__ float g_pf1 [MTOT*Dd];
__device__ float g_pfB [MTOT*Dd];
__device__ float g_obj [MTOT*Dd];
__device__ float g_clsf[MTOT*Dd];
__device__ float g_ffh [MTOT*FFf];
__device__ float g_params[(size_t)MTOT*PAR];       // 314 MB
__device__ float g_f2  [(size_t)MTOT*Ss*Dd];       // 120 MB
__device__ float g_part[(size_t)8*MTOT*Dd];        // split-K partials
__device__ unsigned char g_maskb[Nb*NRr*NRr];

// ---------------- helpers ----------------
__device__ __forceinline__ float blockSum256(float v, float* red) {
#pragma unroll
    for (int o = 16; o; o >>= 1) v += __shfl_down_sync(0xffffffffu, v, o);
    if ((threadIdx.x & 31) == 0) red[threadIdx.x >> 5] = v;
    __syncthreads();
    float s = red[0]+red[1]+red[2]+red[3]+red[4]+red[5]+red[6]+red[7];
    __syncthreads();
    return s;
}

// ---------------- IoU + boolean attention mask ----------------
__global__ void iou_mask_kernel(const float* __restrict__ bb, const float* __restrict__ cm,
                                unsigned char* __restrict__ mask)
{
    int idx = blockIdx.x * blockDim.x + threadIdx.x;
    if (idx >= Nb*NRr*NRr) return;
    int b = idx / (NRr*NRr);
    int r = idx - b*NRr*NRr;
    int q = r / NRr, k = r - q*NRr;
    const float* bq = bb + (size_t)(b*NRr+q)*4;
    const float* bk = bb + (size_t)(b*NRr+k)*4;
    float areaA = (bq[2]-bq[0])*(bq[3]-bq[1]);
    float areaB = (bk[2]-bk[0])*(bk[3]-bk[1]);
    float ix = fmaxf(fminf(bq[2],bk[2]) - fmaxf(bq[0],bk[0]), 0.f);
    float iy = fmaxf(fminf(bq[3],bk[3]) - fmaxf(bq[1],bk[1]), 0.f);
    float inter = ix*iy;
    float iou = inter / fmaxf(areaA + areaB - inter, 1e-9f);
    float cq = cm[b*NRr+q], ck = cm[b*NRr+k];
    float omask = (iou < 0.5f) ? 1.f : 0.f;
    float val = omask*cq*ck + ((q==k) ? (1.f-cq) : 0.f);
    mask[idx] = (val > 0.f) ? (unsigned char)1 : (unsigned char)0;
}

// ---------------- elementwise add ----------------
__global__ void add_kernel(const float* __restrict__ a, const float* __restrict__ b,
                           float* __restrict__ o, int n)
{
    int i = blockIdx.x * blockDim.x + threadIdx.x;
    if (i < n) o[i] = a[i] + b[i];
}

// ---------------- generic GEMM: C = A[M,K] @ W[N,K]^T (+bias) (opt relu, opt split-K) -----
__global__ void gemm_kernel(const float* __restrict__ A, const float* __restrict__ W,
                            const float* __restrict__ bias, float* __restrict__ C,
                            int M, int N, int K, int doRelu)
{
    __shared__ __align__(16) float As[16][64];
    __shared__ __align__(16) float Ws[16][64];
    int tid = threadIdx.x;
    int tx = tid & 15, ty = tid >> 4;
    int rowBase = blockIdx.y * 64;
    int colBase = blockIdx.x * 64;
    int kc   = K / gridDim.z;           // K assumed divisible
    int kbeg = blockIdx.z * kc;
    int kend = kbeg + kc;
    float* Cp = C + (size_t)blockIdx.z * (size_t)M * (size_t)N;

    float acc[4][4] = {};
    int lr = tid >> 2;                  // 0..63
    int lk = (tid & 3) * 4;             // 0,4,8,12

    for (int k0 = kbeg; k0 < kend; k0 += 16) {
        {
            int r = rowBase + lr;
            float4 v = make_float4(0.f,0.f,0.f,0.f);
            if (r < M) v = *(const float4*)(A + (size_t)r*K + k0 + lk);
            As[lk+0][lr]=v.x; As[lk+1][lr]=v.y; As[lk+2][lr]=v.z; As[lk+3][lr]=v.w;
        }
        {
            int n = colBase + lr;
            float4 v = make_float4(0.f,0.f,0.f,0.f);
            if (n < N) v = *(const float4*)(W + (size_t)n*K + k0 + lk);
            Ws[lk+0][lr]=v.x; Ws[lk+1][lr]=v.y; Ws[lk+2][lr]=v.z; Ws[lk+3][lr]=v.w;
        }
        __syncthreads();
#pragma unroll
        for (int kk = 0; kk < 16; ++kk) {
            float4 a = *(const float4*)&As[kk][ty*4];
            float4 w = *(const float4*)&Ws[kk][tx*4];
            acc[0][0]+=a.x*w.x; acc[0][1]+=a.x*w.y; acc[0][2]+=a.x*w.z; acc[0][3]+=a.x*w.w;
            acc[1][0]+=a.y*w.x; acc[1][1]+=a.y*w.y; acc[1][2]+=a.y*w.z; acc[1][3]+=a.y*w.w;
            acc[2][0]+=a.z*w.x; acc[2][1]+=a.z*w.y; acc[2][2]+=a.z*w.z; acc[2][3]+=a.z*w.w;
            acc[3][0]+=a.w*w.x; acc[3][1]+=a.w*w.y; acc[3][2]+=a.w*w.z; acc[3][3]+=a.w*w.w;
        }
        __syncthreads();
    }
#pragma unroll
    for (int i = 0; i < 4; ++i) {
        int r = rowBase + ty*4 + i;
        if (r >= M) continue;
#pragma unroll
        for (int j = 0; j < 4; ++j) {
            int c = colBase + tx*4 + j;
            if (c >= N) continue;
            float v = acc[i][j] + (bias ? bias[c] : 0.f);
            if (doRelu) v = fmaxf(v, 0.f);
            Cp[(size_t)r*N + c] = v;
        }
    }
}

// ---------------- split-K reduce: out[i] = sum_z part[z][i] + bias[i % Ncol] ----------
__global__ void reduce_splitk(const float* __restrict__ part, const float* __restrict__ bias,
                              float* __restrict__ out, int nz, int MN, int Ncol)
{
    int i = blockIdx.x * blockDim.x + threadIdx.x;
    if (i >= MN) return;
    float s = 0.f;
    for (int z = 0; z < nz; ++z) s += part[(size_t)z*MN + i];
    if (bias) s += bias[i % Ncol];
    out[i] = s;
}

// ---------------- masked multi-head attention: 1 block per (b,q), 1 warp per head ---------
__global__ void attn_kernel(const float* __restrict__ qp, const float* __restrict__ kp,
                            const float* __restrict__ vp, const unsigned char* __restrict__ mask,
                            float* __restrict__ ctx)
{
    __shared__ float sc[Hh][NRr];
    __shared__ float sq[Hh][32];
    int bq = blockIdx.x;
    int b = bq / NRr, q = bq - b*NRr;
    int w = threadIdx.x >> 5;
    int lane = threadIdx.x & 31;

    sq[w][lane] = qp[(size_t)bq*Dd + w*32 + lane];
    __syncwarp();

    const unsigned char* mrow = mask + (size_t)b*NRr*NRr + (size_t)q*NRr;
    const float scale = 0.17677669529663687f;   // 1/sqrt(32)

    for (int k = lane; k < NRr; k += 32) {
        const float4* kr = (const float4*)(kp + ((size_t)(b*NRr + k))*Dd + w*32);
        float s = 0.f;
#pragma unroll
        for (int u = 0; u < 8; ++u) {
            float4 kv = kr[u];
            s += sq[w][u*4+0]*kv.x + sq[w][u*4+1]*kv.y + sq[w][u*4+2]*kv.z + sq[w][u*4+3]*kv.w;
        }
        s *= scale;
        if (mrow[k]) s = -1e9f;
        sc[w][k] = s;
    }
    __syncwarp();
    float mx = -1e30f;
    for (int k = lane; k < NRr; k += 32) mx = fmaxf(mx, sc[w][k]);
#pragma unroll
    for (int o = 16; o; o >>= 1) mx = fmaxf(mx, __shfl_xor_sync(0xffffffffu, mx, o));
    float sum = 0.f;
    for (int k = lane; k < NRr; k += 32) { float e = expf(sc[w][k]-mx); sc[w][k] = e; sum += e; }
#pragma unroll
    for (int o = 16; o; o >>= 1) sum += __shfl_xor_sync(0xffffffffu, sum, o);
    __syncwarp();
    float inv = 1.f / sum;

    float acc = 0.f;
#pragma unroll 4
    for (int k = 0; k < NRr; ++k)
        acc += sc[w][k] * vp[((size_t)(b*NRr + k))*Dd + w*32 + lane];
    ctx[(size_t)bq*Dd + w*32 + lane] = acc * inv;
}

// ---------------- LayerNorm row kernel (D=256): out = ln(X (+R)) (opt relu) (opt *mask[row])
__global__ void ln_kernel(const float* __restrict__ X, const float* __restrict__ R,
                          const float* __restrict__ mrow, float* __restrict__ out, int doRelu)
{
    __shared__ float red[8];
    int i = blockIdx.x, t = threadIdx.x;
    float x = X[(size_t)i*Dd + t];
    if (R) x += R[(size_t)i*Dd + t];
    float m  = blockSum256(x, red) * (1.f/Dd);
    float dv = x - m;
    float var = blockSum256(dv*dv, red) * (1.f/Dd);
    float y = dv * rsqrtf(var + 1e-5f);
    if (doRelu) y = fmaxf(y, 0.f);
    if (mrow) y *= mrow[i];
    out[(size_t)i*Dd + t] = y;
}

// ---------------- double LN: out = ln( relu(ln(X)) + P ) --------------------------------
__global__ void ln2_kernel(const float* __restrict__ X, const float* __restrict__ P,
                           float* __restrict__ out)
{
    __shared__ float red[8];
    int i = blockIdx.x, t = threadIdx.x;
    float x = X[(size_t)i*Dd + t];
    float m  = blockSum256(x, red) * (1.f/Dd);
    float dv = x - m;
    float var = blockSum256(dv*dv, red) * (1.f/Dd);
    float y = fmaxf(dv * rsqrtf(var + 1e-5f), 0.f);
    float z = y + P[(size_t)i*Dd + t];
    m  = blockSum256(z, red) * (1.f/Dd);
    dv = z - m;
    var = blockSum256(dv*dv, red) * (1.f/Dd);
    out[(size_t)i*Dd + t] = dv * rsqrtf(var + 1e-5f);
}

// ---------------- DynamicConv per instance: f2 = relu(ln( relu(ln(feats@p1)) @ p2 )) -----
__global__ void dynconv_kernel(const float* __restrict__ roi, const float* __restrict__ params,
                               float* __restrict__ f2out)
{
    __shared__ float f1[Ss*DDd];   // 3136 floats
    __shared__ float red[8];
    int i = blockIdx.x, t = threadIdx.x;
    const float* p1 = params + (size_t)i*PAR;          // [256][64]
    const float* p2 = p1 + Dd*DDd;                      // [64][256]
    int e64 = t & 63, sl = t >> 6;

    // step 1: f1[s][e] = relu(ln_e( sum_d feats[s][d]*p1[d][e] ))
    for (int s0 = 0; s0 < Ss; s0 += 4) {
        int s = s0 + sl;
        float acc = 0.f;
        if (s < Ss) {
            const float* fr = roi + (size_t)s*MTOT*Dd + (size_t)i*Dd;
#pragma unroll 8
            for (int d = 0; d < Dd; ++d) acc += fr[d] * p1[d*DDd + e64];
        }
        float v = acc;
#pragma unroll
        for (int o = 16; o; o >>= 1) v += __shfl_down_sync(0xffffffffu, v, o);
        if ((t & 31) == 0) red[t >> 5] = v;
        __syncthreads();
        float m = (red[sl*2] + red[sl*2+1]) * (1.f/DDd);
        __syncthreads();
        float dv = acc - m;
        v = dv*dv;
#pragma unroll
        for (int o = 16; o; o >>= 1) v += __shfl_down_sync(0xffffffffu, v, o);
        if ((t & 31) == 0) red[t >> 5] = v;
        __syncthreads();
        float var = (red[sl*2] + red[sl*2+1]) * (1.f/DDd);
        __syncthreads();
        if (s < Ss) f1[s*DDd + e64] = fmaxf(dv * rsqrtf(var + 1e-5f), 0.f);
    }
    __syncthreads();

    // step 2: f2[s][d] = relu(ln_d( sum_e f1[s][e]*p2[e][d] ))
    for (int s = 0; s < Ss; ++s) {
        const float* fr = f1 + s*DDd;
        float acc = 0.f;
#pragma unroll
        for (int e = 0; e < DDd; ++e) acc += fr[e] * p2[e*Dd + t];
        float m  = blockSum256(acc, red) * (1.f/Dd);
        float dv = acc - m;
        float var = blockSum256(dv*dv, red) * (1.f/Dd);
        f2out[(size_t)i*(Ss*Dd) + s*Dd + t] = fmaxf(dv * rsqrtf(var + 1e-5f), 0.f);
    }
}

// ---------------- host side ----------------
static float* symaddr(const void* sym) { void* p = nullptr; cudaGetSymbolAddress(&p, sym); return (float*)p; }

extern "C" void kernel_launch(void* const* d_in, const int* in_sizes, int n_in,
                              void* d_out, int out_size)
{
    const float* bboxes = (const float*)d_in[0];
    const float* pro    = (const float*)d_in[1];
    const float* roi    = (const float*)d_in[2];
    const float* query  = (const float*)d_in[3];
    const float* cm     = (const float*)d_in[4];
    const float* w_qkv  = (const float*)d_in[5];
    const float* b_qkv  = (const float*)d_in[6];
    const float* w_ao   = (const float*)d_in[7];
    const float* b_ao   = (const float*)d_in[8];
    const float* w_dyn  = (const float*)d_in[9];
    const float* b_dyn  = (const float*)d_in[10];
    const float* w_do   = (const float*)d_in[11];
    const float* b_do   = (const float*)d_in[12];
    const float* w_ff1  = (const float*)d_in[13];
    const float* b_ff1  = (const float*)d_in[14];
    const float* w_ff2  = (const float*)d_in[15];
    const float* b_ff2  = (const float*)d_in[16];
    const float* w_cls  = (const float*)d_in[17];
    const float* w_lg   = (const float*)d_in[18];
    const float* b_lg   = (const float*)d_in[19];
    float* out = (float*)d_out;

    float* p_qk   = symaddr(g_qk);
    float* p_qp   = symaddr(g_qp);
    float* p_kp   = symaddr(g_kp);
    float* p_vp   = symaddr(g_vp);
    float* p_ctx  = symaddr(g_ctx);
    float* p_t    = symaddr(g_t);
    float* p_pf1  = symaddr(g_pf1);
    float* p_pfB  = symaddr(g_pfB);
    float* p_obj  = symaddr(g_obj);
    float* p_clsf = symaddr(g_clsf);
    float* p_ffh  = symaddr(g_ffh);
    float* p_par  = symaddr(g_params);
    float* p_f2   = symaddr(g_f2);
    float* p_part = symaddr(g_part);
    unsigned char* p_mask; { void* v; cudaGetSymbolAddress(&v, g_maskb); p_mask = (unsigned char*)v; }

    // 1. IoU + attention mask
    iou_mask_kernel<<<(Nb*NRr*NRr + 255)/256, 256>>>(bboxes, cm, p_mask);
    // 2. qk = pro + query
    add_kernel<<<(MTOT*Dd + 255)/256, 256>>>(pro, query, p_qk, MTOT*Dd);
    // 3-5. Q/K/V projections
    {
        dim3 g((Dd+63)/64, (MTOT+63)/64, 1);
        gemm_kernel<<<g, 256>>>(p_qk, w_qkv,              b_qkv,        p_qp, MTOT, Dd, Dd, 0);
        gemm_kernel<<<g, 256>>>(p_qk, w_qkv + Dd*Dd,      b_qkv + Dd,   p_kp, MTOT, Dd, Dd, 0);
        gemm_kernel<<<g, 256>>>(pro,  w_qkv + 2*Dd*Dd,    b_qkv + 2*Dd, p_vp, MTOT, Dd, Dd, 0);
    }
    // 6. masked MHSA
    attn_kernel<<<MTOT, 256>>>(p_qp, p_kp, p_vp, p_mask, p_ctx);
    // 7. out projection
    {
        dim3 g((Dd+63)/64, (MTOT+63)/64, 1);
        gemm_kernel<<<g, 256>>>(p_ctx, w_ao, b_ao, p_t, MTOT, Dd, Dd, 0);
    }
    // 8. norm1 + mask
    ln_kernel<<<MTOT, 256>>>(p_t, pro, cm, p_pf1, 0);
    // 9. dynamic conv params GEMM [2400,32768]
    {
        dim3 g((PAR+63)/64, (MTOT+63)/64, 1);
        gemm_kernel<<<g, 256>>>(p_pf1, w_dyn, b_dyn, p_par, MTOT, PAR, Dd, 0);
    }
    // 10. per-instance dynamic conv
    dynconv_kernel<<<MTOT, 256>>>(roi, p_par, p_f2);
    // 11. dyn out projection, K=12544, split-K=8
    {
        dim3 g((Dd+63)/64, (MTOT+63)/64, 8);
        gemm_kernel<<<g, 256>>>(p_f2, w_do, nullptr, p_part, MTOT, Dd, Ss*Dd, 0);
        reduce_splitk<<<(MTOT*Dd + 255)/256, 256>>>(p_part, b_do, p_t, 8, MTOT*Dd, Dd);
    }
    // 12. pf2 = relu(ln(t)); pfB = ln(pf1 + pf2)
    ln2_kernel<<<MTOT, 256>>>(p_t, p_pf1, p_pfB);
    // 13. FFN up + relu
    {
        dim3 g((FFf+63)/64, (MTOT+63)/64, 1);
        gemm_kernel<<<g, 256>>>(p_pfB, w_ff1, b_ff1, p_ffh, MTOT, FFf, Dd, 1);
    }
    // 14. FFN down, K=2048, split-K=4
    {
        dim3 g((Dd+63)/64, (MTOT+63)/64, 4);
        gemm_kernel<<<g, 256>>>(p_ffh, w_ff2, nullptr, p_part, MTOT, Dd, FFf, 0);
        reduce_splitk<<<(MTOT*Dd + 255)/256, 256>>>(p_part, b_ff2, p_t, 4, MTOT*Dd, Dd);
    }
    // 15. norm3 + mask (fc = obj * mask fused)
    ln_kernel<<<MTOT, 256>>>(p_t, p_pfB, cm, p_obj, 0);
    // 16. cls tower linear (bias-free)
    {
        dim3 g((Dd+63)/64, (MTOT+63)/64, 1);
        gemm_kernel<<<g, 256>>>(p_obj, w_cls, nullptr, p_t, MTOT, Dd, Dd, 0);
    }
    // 17. relu(ln(.))
    ln_kernel<<<MTOT, 256>>>(p_t, nullptr, nullptr, p_clsf, 1);
    // 18. class logits
    {
        dim3 g((NCc+63)/64, (MTOT+63)/64, 1);
        gemm_kernel<<<g, 256>>>(p_clsf, w_lg, b_lg, out, MTOT, NCc, Dd, 0);
    }
}

// round 2
// speedup vs baseline: 2.6397x; 2.6397x over previous
#include <cuda_runtime.h>
#include <math.h>

#define Nb   8
#define NRr  300
#define Dd   256
#define Hh   8
#define Ss   49
#define DDd  64
#define FFf  2048
#define NCc  80
#define MTOT (Nb*NRr)          // 2400
#define PAR  32768             // 2*D*DD

// ---------------- scratch (device globals; no allocation allowed) ----------------
__device__ float g_qk  [MTOT*Dd];
__device__ float g_qp  [MTOT*Dd];
__device__ float g_kp  [MTOT*Dd];
__device__ float g_vp  [MTOT*Dd];
__device__ float g_ctx [MTOT*Dd];
__device__ float g_t   [MTOT*Dd];
__device__ float g_pf1 [MTOT*Dd];
__device__ float g_pfB [MTOT*Dd];
__device__ float g_obj [MTOT*Dd];
__device__ float g_clsf[MTOT*Dd];
__device__ float g_ffh [MTOT*FFf];
__device__ float g_params[(size_t)MTOT*PAR];       // 314 MB
__device__ float g_f2  [(size_t)MTOT*Ss*Dd];       // 120 MB
__device__ float g_part[(size_t)8*MTOT*Dd];        // split-K partials
__device__ unsigned char g_maskb[Nb*NRr*NRr];

// ---------------- helpers ----------------
__device__ __forceinline__ unsigned f2tf(float x) {
    unsigned u;
    asm("cvt.rna.tf32.f32 %0, %1;" : "=r"(u) : "f"(x));
    return u;
}

__device__ __forceinline__ void mma_tf32(float* d, const unsigned* a, const unsigned* b) {
    asm volatile("mma.sync.aligned.m16n8k8.row.col.f32.tf32.tf32.f32 "
                 "{%0,%1,%2,%3}, {%4,%5,%6,%7}, {%8,%9}, {%0,%1,%2,%3};"
                 : "+f"(d[0]), "+f"(d[1]), "+f"(d[2]), "+f"(d[3])
                 : "r"(a[0]), "r"(a[1]), "r"(a[2]), "r"(a[3]), "r"(b[0]), "r"(b[1]));
}

__device__ __forceinline__ float blockSum256(float v, float* red) {
#pragma unroll
    for (int o = 16; o; o >>= 1) v += __shfl_down_sync(0xffffffffu, v, o);
    if ((threadIdx.x & 31) == 0) red[threadIdx.x >> 5] = v;
    __syncthreads();
    float s = red[0]+red[1]+red[2]+red[3]+red[4]+red[5]+red[6]+red[7];
    __syncthreads();
    return s;
}

// ---------------- IoU + boolean attention mask ----------------
__global__ void iou_mask_kernel(const float* __restrict__ bb, const float* __restrict__ cm,
                                unsigned char* __restrict__ mask)
{
    int idx = blockIdx.x * blockDim.x + threadIdx.x;
    if (idx >= Nb*NRr*NRr) return;
    int b = idx / (NRr*NRr);
    int r = idx - b*NRr*NRr;
    int q = r / NRr, k = r - q*NRr;
    const float* bq = bb + (size_t)(b*NRr+q)*4;
    const float* bk = bb + (size_t)(b*NRr+k)*4;
    float areaA = (bq[2]-bq[0])*(bq[3]-bq[1]);
    float areaB = (bk[2]-bk[0])*(bk[3]-bk[1]);
    float ix = fmaxf(fminf(bq[2],bk[2]) - fmaxf(bq[0],bk[0]), 0.f);
    float iy = fmaxf(fminf(bq[3],bk[3]) - fmaxf(bq[1],bk[1]), 0.f);
    float inter = ix*iy;
    float iou = inter / fmaxf(areaA + areaB - inter, 1e-9f);
    float cq = cm[b*NRr+q], ck = cm[b*NRr+k];
    float omask = (iou < 0.5f) ? 1.f : 0.f;
    float val = omask*cq*ck + ((q==k) ? (1.f-cq) : 0.f);
    mask[idx] = (val > 0.f) ? (unsigned char)1 : (unsigned char)0;
}

// ---------------- elementwise add ----------------
__global__ void add_kernel(const float* __restrict__ a, const float* __restrict__ b,
                           float* __restrict__ o, int n)
{
    int i = blockIdx.x * blockDim.x + threadIdx.x;
    if (i < n) o[i] = a[i] + b[i];
}

// ================= tf32 tensor-core GEMM: C = A[M,K] @ W[N,K]^T ==================
// BM=128, BN=64, BK=16, 256 threads (8 warps, warp tile 32x32).
// Optional split-K over gridDim.z (writes partials), bias, relu.
#define BM 128
#define BN 64
#define BK 16
#define PADA (BM+8)
#define PADB (BN+8)

__global__ void __launch_bounds__(256) gemm_tc(
    const float* __restrict__ A, const float* __restrict__ W,
    const float* __restrict__ bias, float* __restrict__ C,
    int M, int N, int K, int doRelu)
{
    __shared__ unsigned As[BK][PADA];
    __shared__ unsigned Bs[BK][PADB];
    int tid  = threadIdx.x;
    int lane = tid & 31;
    int warp = tid >> 5;
    int rowBase = blockIdx.y * BM;
    int colBase = blockIdx.x * BN;
    int kc   = K / gridDim.z;
    int kbeg = blockIdx.z * kc;
    int kend = kbeg + kc;
    float* Cp = C + (size_t)blockIdx.z * (size_t)M * (size_t)N;

    int mBase = (warp >> 1) * 32;
    int nBase = (warp & 1) * 32;

    float acc[2][4][4];
#pragma unroll
    for (int a_ = 0; a_ < 2; ++a_)
#pragma unroll
        for (int b_ = 0; b_ < 4; ++b_)
#pragma unroll
            for (int c_ = 0; c_ < 4; ++c_) acc[a_][b_][c_] = 0.f;

    int alr = tid >> 1;           // 0..127 (A row within tile)
    int alk = (tid & 1) * 8;      // 0 or 8
    int blr = tid >> 2;           // 0..63 (W row = output col)
    int blk = (tid & 3) * 4;      // 0,4,8,12

    int gr = lane >> 2, gc = lane & 3;

    for (int k0 = kbeg; k0 < kend; k0 += BK) {
        // stage A tile (transposed to [k][m]) with tf32 conversion
        {
            int r = rowBase + alr;
            float4 v0 = make_float4(0.f,0.f,0.f,0.f), v1 = v0;
            if (r < M) {
                const float4* ap = (const float4*)(A + (size_t)r*K + k0 + alk);
                v0 = ap[0]; v1 = ap[1];
            }
            As[alk+0][alr] = f2tf(v0.x); As[alk+1][alr] = f2tf(v0.y);
            As[alk+2][alr] = f2tf(v0.z); As[alk+3][alr] = f2tf(v0.w);
            As[alk+4][alr] = f2tf(v1.x); As[alk+5][alr] = f2tf(v1.y);
            As[alk+6][alr] = f2tf(v1.z); As[alk+7][alr] = f2tf(v1.w);
        }
        // stage B tile ([k][n], B[k][n] = W[n][k])
        {
            int n = colBase + blr;
            float4 v = make_float4(0.f,0.f,0.f,0.f);
            if (n < N) v = *(const float4*)(W + (size_t)n*K + k0 + blk);
            Bs[blk+0][blr] = f2tf(v.x); Bs[blk+1][blr] = f2tf(v.y);
            Bs[blk+2][blr] = f2tf(v.z); Bs[blk+3][blr] = f2tf(v.w);
        }
        __syncthreads();
#pragma unroll
        for (int ks = 0; ks < BK; ks += 8) {
            unsigned a[2][4], b[4][2];
#pragma unroll
            for (int mt = 0; mt < 2; ++mt) {
                int row = mBase + mt*16;
                a[mt][0] = As[ks+gc  ][row+gr  ];
                a[mt][1] = As[ks+gc  ][row+gr+8];
                a[mt][2] = As[ks+4+gc][row+gr  ];
                a[mt][3] = As[ks+4+gc][row+gr+8];
            }
#pragma unroll
            for (int nt = 0; nt < 4; ++nt) {
                int col = nBase + nt*8;
                b[nt][0] = Bs[ks+gc  ][col+gr];
                b[nt][1] = Bs[ks+4+gc][col+gr];
            }
#pragma unroll
            for (int mt = 0; mt < 2; ++mt)
#pragma unroll
                for (int nt = 0; nt < 4; ++nt)
                    mma_tf32(acc[mt][nt], a[mt], b[nt]);
        }
        __syncthreads();
    }

    // epilogue: paired float2 stores (N is always even)
#pragma unroll
    for (int mt = 0; mt < 2; ++mt) {
#pragma unroll
        for (int nt = 0; nt < 4; ++nt) {
            int c = colBase + nBase + nt*8 + gc*2;
            if (c >= N) continue;
            float bx = bias ? bias[c]   : 0.f;
            float by = bias ? bias[c+1] : 0.f;
            int r0 = rowBase + mBase + mt*16 + gr;
            if (r0 < M) {
                float x = acc[mt][nt][0] + bx, y = acc[mt][nt][1] + by;
                if (doRelu) { x = fmaxf(x,0.f); y = fmaxf(y,0.f); }
                *(float2*)(Cp + (size_t)r0*N + c) = make_float2(x, y);
            }
            int r1 = r0 + 8;
            if (r1 < M) {
                float x = acc[mt][nt][2] + bx, y = acc[mt][nt][3] + by;
                if (doRelu) { x = fmaxf(x,0.f); y = fmaxf(y,0.f); }
                *(float2*)(Cp + (size_t)r1*N + c) = make_float2(x, y);
            }
        }
    }
}

// ---------------- split-K reduce ----------------
__global__ void reduce_splitk(const float* __restrict__ part, const float* __restrict__ bias,
                              float* __restrict__ out, int nz, int MN, int Ncol)
{
    int i = blockIdx.x * blockDim.x + threadIdx.x;
    if (i >= MN) return;
    float s = 0.f;
    for (int z = 0; z < nz; ++z) s += part[(size_t)z*MN + i];
    if (bias) s += bias[i % Ncol];
    out[i] = s;
}

// ---------------- masked multi-head attention ----------------
__global__ void attn_kernel(const float* __restrict__ qp, const float* __restrict__ kp,
                            const float* __restrict__ vp, const unsigned char* __restrict__ mask,
                            float* __restrict__ ctx)
{
    __shared__ float sc[Hh][NRr];
    __shared__ float sq[Hh][32];
    int bq = blockIdx.x;
    int b = bq / NRr, q = bq - b*NRr;
    int w = threadIdx.x >> 5;
    int lane = threadIdx.x & 31;

    sq[w][lane] = qp[(size_t)bq*Dd + w*32 + lane];
    __syncwarp();

    const unsigned char* mrow = mask + (size_t)b*NRr*NRr + (size_t)q*NRr;
    const float scale = 0.17677669529663687f;   // 1/sqrt(32)

    for (int k = lane; k < NRr; k += 32) {
        const float4* kr = (const float4*)(kp + ((size_t)(b*NRr + k))*Dd + w*32);
        float s = 0.f;
#pragma unroll
        for (int u = 0; u < 8; ++u) {
            float4 kv = kr[u];
            s += sq[w][u*4+0]*kv.x + sq[w][u*4+1]*kv.y + sq[w][u*4+2]*kv.z + sq[w][u*4+3]*kv.w;
        }
        s *= scale;
        if (mrow[k]) s = -1e9f;
        sc[w][k] = s;
    }
    __syncwarp();
    float mx = -1e30f;
    for (int k = lane; k < NRr; k += 32) mx = fmaxf(mx, sc[w][k]);
#pragma unroll
    for (int o = 16; o; o >>= 1) mx = fmaxf(mx, __shfl_xor_sync(0xffffffffu, mx, o));
    float sum = 0.f;
    for (int k = lane; k < NRr; k += 32) { float e = expf(sc[w][k]-mx); sc[w][k] = e; sum += e; }
#pragma unroll
    for (int o = 16; o; o >>= 1) sum += __shfl_xor_sync(0xffffffffu, sum, o);
    __syncwarp();
    float inv = 1.f / sum;

    float acc = 0.f;
#pragma unroll 4
    for (int k = 0; k < NRr; ++k)
        acc += sc[w][k] * vp[((size_t)(b*NRr + k))*Dd + w*32 + lane];
    ctx[(size_t)bq*Dd + w*32 + lane] = acc * inv;
}

// ---------------- LayerNorm row kernel (D=256) ----------------
__global__ void ln_kernel(const float* __restrict__ X, const float* __restrict__ R,
                          const float* __restrict__ mrow, float* __restrict__ out, int doRelu)
{
    __shared__ float red[8];
    int i = blockIdx.x, t = threadIdx.x;
    float x = X[(size_t)i*Dd + t];
    if (R) x += R[(size_t)i*Dd + t];
    float m  = blockSum256(x, red) * (1.f/Dd);
    float dv = x - m;
    float var = blockSum256(dv*dv, red) * (1.f/Dd);
    float y = dv * rsqrtf(var + 1e-5f);
    if (doRelu) y = fmaxf(y, 0.f);
    if (mrow) y *= mrow[i];
    out[(size_t)i*Dd + t] = y;
}

// ---------------- double LN: out = ln( relu(ln(X)) + P ) -------------------------
__global__ void ln2_kernel(const float* __restrict__ X, const float* __restrict__ P,
                           float* __restrict__ out)
{
    __shared__ float red[8];
    int i = blockIdx.x, t = threadIdx.x;
    float x = X[(size_t)i*Dd + t];
    float m  = blockSum256(x, red) * (1.f/Dd);
    float dv = x - m;
    float var = blockSum256(dv*dv, red) * (1.f/Dd);
    float y = fmaxf(dv * rsqrtf(var + 1e-5f), 0.f);
    float z = y + P[(size_t)i*Dd + t];
    m  = blockSum256(z, red) * (1.f/Dd);
    dv = z - m;
    var = blockSum256(dv*dv, red) * (1.f/Dd);
    out[(size_t)i*Dd + t] = dv * rsqrtf(var + 1e-5f);
}

// ================= DynamicConv on tensor cores ===================================
// One block (128 thr, 4 warps) per instance i.
// Step1: C1[64(s) x 64(e)] = feats[49x256] @ p1[256x64]; LN over e + relu -> f1 (tf32, smem [e][s])
// Step2: C2[64(s) x 256(d)] = f1 @ p2[64x256], 64-col chunks -> raw smem; warp-row LN+relu -> f2.
// Dynamic smem (u32 words): As 32x72 | Bs 32x72 | f1t 64x72 | Bs2 64x72 | f2r 49x264(float)
#define DC_AS   0
#define DC_BS   (32*72)
#define DC_F1   (DC_BS + 32*72)
#define DC_BS2  (DC_F1 + 64*72)
#define DC_F2R  (DC_BS2 + 64*72)
#define DC_WORDS (DC_F2R + 49*264)     // 26760 words = 107040 bytes

__global__ void __launch_bounds__(128) dynconv_tc(
    const float* __restrict__ roi, const float* __restrict__ params,
    float* __restrict__ f2out)
{
    extern __shared__ unsigned sm[];
    unsigned* Asm = sm + DC_AS;     // [k=32][s=64] pitch 72
    unsigned* Bsm = sm + DC_BS;     // [k=32][e=64] pitch 72
    unsigned* f1t = sm + DC_F1;     // [e=64][s=64] pitch 72
    unsigned* Bs2 = sm + DC_BS2;    // [e=64][n=64] pitch 72
    float*    f2r = (float*)(sm + DC_F2R);  // [s=49][d=256] pitch 264

    int i    = blockIdx.x;
    int tid  = threadIdx.x;
    int lane = tid & 31;
    int warp = tid >> 5;            // 0..3
    int gr = lane >> 2, gc = lane & 3;
    int rowW = warp * 16;

    const float* p1 = params + (size_t)i * PAR;          // [256][64]
    const float* p2 = p1 + Dd*DDd;                        // [64][256]

    // ---------------- Step 1 ----------------
    float acc1[8][4];
#pragma unroll
    for (int a_ = 0; a_ < 8; ++a_)
#pragma unroll
        for (int c_ = 0; c_ < 4; ++c_) acc1[a_][c_] = 0.f;

    for (int dc = 0; dc < Dd; dc += 32) {
        __syncthreads();
        // feats chunk -> Asm[k][s]
#pragma unroll
        for (int p = 0; p < 4; ++p) {
            int s  = p*16 + (tid >> 3);
            int d4 = (tid & 7) * 4;
            float4 v = make_float4(0.f,0.f,0.f,0.f);
            if (s < Ss) v = *(const float4*)(roi + ((size_t)s*MTOT + i)*Dd + dc + d4);
            Asm[(d4+0)*72 + s] = f2tf(v.x);
            Asm[(d4+1)*72 + s] = f2tf(v.y);
            Asm[(d4+2)*72 + s] = f2tf(v.z);
            Asm[(d4+3)*72 + s] = f2tf(v.w);
        }
        // p1 chunk -> Bsm[k][e]
#pragma unroll
        for (int p = 0; p < 4; ++p) {
            int d  = p*8 + (tid >> 4);
            int e4 = (tid & 15) * 4;
            float4 v = *(const float4*)(p1 + (size_t)(dc + d)*DDd + e4);
            Bsm[d*72 + e4+0] = f2tf(v.x);
            Bsm[d*72 + e4+1] = f2tf(v.y);
            Bsm[d*72 + e4+2] = f2tf(v.z);
            Bsm[d*72 + e4+3] = f2tf(v.w);
        }
        __syncthreads();
#pragma unroll
        for (int ks = 0; ks < 32; ks += 8) {
            unsigned a[4], b[8][2];
            a[0] = Asm[(ks+gc  )*72 + rowW+gr  ];
            a[1] = Asm[(ks+gc  )*72 + rowW+gr+8];
            a[2] = Asm[(ks+4+gc)*72 + rowW+gr  ];
            a[3] = Asm[(ks+4+gc)*72 + rowW+gr+8];
#pragma unroll
            for (int nt = 0; nt < 8; ++nt) {
                b[nt][0] = Bsm[(ks+gc  )*72 + nt*8+gr];
                b[nt][1] = Bsm[(ks+4+gc)*72 + nt*8+gr];
            }
#pragma unroll
            for (int nt = 0; nt < 8; ++nt) mma_tf32(acc1[nt], a, b[nt]);
        }
    }
    // LN over e (64) for rows r0 = rowW+gr, r1 = r0+8 (4-lane group holds a row)
    {
        float s0 = 0.f, s1 = 0.f;
#pragma unroll
        for (int nt = 0; nt < 8; ++nt) { s0 += acc1[nt][0]+acc1[nt][1]; s1 += acc1[nt][2]+acc1[nt][3]; }
        s0 += __shfl_xor_sync(0xffffffffu, s0, 1); s0 += __shfl_xor_sync(0xffffffffu, s0, 2);
        s1 += __shfl_xor_sync(0xffffffffu, s1, 1); s1 += __shfl_xor_sync(0xffffffffu, s1, 2);
        float m0 = s0 * (1.f/DDd), m1 = s1 * (1.f/DDd);
        float v0 = 0.f, v1 = 0.f;
#pragma unroll
        for (int nt = 0; nt < 8; ++nt) {
            float d0 = acc1[nt][0]-m0, d1 = acc1[nt][1]-m0;
            float d2 = acc1[nt][2]-m1, d3 = acc1[nt][3]-m1;
            v0 += d0*d0 + d1*d1; v1 += d2*d2 + d3*d3;
        }
        v0 += __shfl_xor_sync(0xffffffffu, v0, 1); v0 += __shfl_xor_sync(0xffffffffu, v0, 2);
        v1 += __shfl_xor_sync(0xffffffffu, v1, 1); v1 += __shfl_xor_sync(0xffffffffu, v1, 2);
        float r0f = rsqrtf(v0*(1.f/DDd) + 1e-5f);
        float r1f = rsqrtf(v1*(1.f/DDd) + 1e-5f);
        int sr0 = rowW + gr, sr1 = sr0 + 8;
#pragma unroll
        for (int nt = 0; nt < 8; ++nt) {
            int e = nt*8 + gc*2;
            f1t[(e  )*72 + sr0] = f2tf(fmaxf((acc1[nt][0]-m0)*r0f, 0.f));
            f1t[(e+1)*72 + sr0] = f2tf(fmaxf((acc1[nt][1]-m0)*r0f, 0.f));
            f1t[(e  )*72 + sr1] = f2tf(fmaxf((acc1[nt][2]-m1)*r1f, 0.f));
            f1t[(e+1)*72 + sr1] = f2tf(fmaxf((acc1[nt][3]-m1)*r1f, 0.f));
        }
    }

    // ---------------- Step 2 ----------------
    for (int nc = 0; nc < Dd; nc += 64) {
        __syncthreads();
        // p2 chunk -> Bs2[k=e][n]
#pragma unroll
        for (int p = 0; p < 8; ++p) {
            int e  = p*8 + (tid >> 4);
            int n4 = (tid & 15) * 4;
            float4 v = *(const float4*)(p2 + (size_t)e*Dd + nc + n4);
            Bs2[e*72 + n4+0] = f2tf(v.x);
            Bs2[e*72 + n4+1] = f2tf(v.y);
            Bs2[e*72 + n4+2] = f2tf(v.z);
            Bs2[e*72 + n4+3] = f2tf(v.w);
        }
        __syncthreads();
        float acc2[8][4];
#pragma unroll
        for (int a_ = 0; a_ < 8; ++a_)
#pragma unroll
            for (int c_ = 0; c_ < 4; ++c_) acc2[a_][c_] = 0.f;
#pragma unroll
        for (int ks = 0; ks < 64; ks += 8) {
            unsigned a[4], b[8][2];
            a[0] = f1t[(ks+gc  )*72 + rowW+gr  ];
            a[1] = f1t[(ks+gc  )*72 + rowW+gr+8];
            a[2] = f1t[(ks+4+gc)*72 + rowW+gr  ];
            a[3] = f1t[(ks+4+gc)*72 + rowW+gr+8];
#pragma unroll
            for (int nt = 0; nt < 8; ++nt) {
                b[nt][0] = Bs2[(ks+gc  )*72 + nt*8+gr];
                b[nt][1] = Bs2[(ks+4+gc)*72 + nt*8+gr];
            }
#pragma unroll
            for (int nt = 0; nt < 8; ++nt) mma_tf32(acc2[nt], a, b[nt]);
        }
        // raw store to f2r (only s<49 rows matter)
        int sr0 = rowW + gr, sr1 = sr0 + 8;
#pragma unroll
        for (int nt = 0; nt < 8; ++nt) {
            int c = nc + nt*8 + gc*2;
            if (sr0 < Ss) *(float2*)(f2r + sr0*264 + c) = make_float2(acc2[nt][0], acc2[nt][1]);
            if (sr1 < Ss) *(float2*)(f2r + sr1*264 + c) = make_float2(acc2[nt][2], acc2[nt][3]);
        }
    }
    __syncthreads();

    // final LN over d (256) per row s, warp per row, then relu + write out
    for (int s = warp; s < Ss; s += 4) {
        float v[8];
        float sum = 0.f;
#pragma unroll
        for (int j = 0; j < 8; ++j) { v[j] = f2r[s*264 + lane + 32*j]; sum += v[j]; }
#pragma unroll
        for (int o = 16; o; o >>= 1) sum += __shfl_xor_sync(0xffffffffu, sum, o);
        float m = sum * (1.f/Dd);
        float var = 0.f;
#pragma unroll
        for (int j = 0; j < 8; ++j) { float d = v[j]-m; var += d*d; }
#pragma unroll
        for (int o = 16; o; o >>= 1) var += __shfl_xor_sync(0xffffffffu, var, o);
        float rs = rsqrtf(var*(1.f/Dd) + 1e-5f);
        float* op = f2out + ((size_t)i*Ss + s)*Dd;
#pragma unroll
        for (int j = 0; j < 8; ++j)
            op[lane + 32*j] = fmaxf((v[j]-m)*rs, 0.f);
    }
}

// ---------------- host side ----------------
static float* symaddr(const void* sym) { void* p = nullptr; cudaGetSymbolAddress(&p, sym); return (float*)p; }

extern "C" void kernel_launch(void* const* d_in, const int* in_sizes, int n_in,
                              void* d_out, int out_size)
{
    const float* bboxes = (const float*)d_in[0];
    const float* pro    = (const float*)d_in[1];
    const float* roi    = (const float*)d_in[2];
    const float* query  = (const float*)d_in[3];
    const float* cm     = (const float*)d_in[4];
    const float* w_qkv  = (const float*)d_in[5];
    const float* b_qkv  = (const float*)d_in[6];
    const float* w_ao   = (const float*)d_in[7];
    const float* b_ao   = (const float*)d_in[8];
    const float* w_dyn  = (const float*)d_in[9];
    const float* b_dyn  = (const float*)d_in[10];
    const float* w_do   = (const float*)d_in[11];
    const float* b_do   = (const float*)d_in[12];
    const float* w_ff1  = (const float*)d_in[13];
    const float* b_ff1  = (const float*)d_in[14];
    const float* w_ff2  = (const float*)d_in[15];
    const float* b_ff2  = (const float*)d_in[16];
    const float* w_cls  = (const float*)d_in[17];
    const float* w_lg   = (const float*)d_in[18];
    const float* b_lg   = (const float*)d_in[19];
    float* out = (float*)d_out;

    float* p_qk   = symaddr(g_qk);
    float* p_qp   = symaddr(g_qp);
    float* p_kp   = symaddr(g_kp);
    float* p_vp   = symaddr(g_vp);
    float* p_ctx  = symaddr(g_ctx);
    float* p_t    = symaddr(g_t);
    float* p_pf1  = symaddr(g_pf1);
    float* p_pfB  = symaddr(g_pfB);
    float* p_obj  = symaddr(g_obj);
    float* p_clsf = symaddr(g_clsf);
    float* p_ffh  = symaddr(g_ffh);
    float* p_par  = symaddr(g_params);
    float* p_f2   = symaddr(g_f2);
    float* p_part = symaddr(g_part);
    unsigned char* p_mask; { void* v; cudaGetSymbolAddress(&v, g_maskb); p_mask = (unsigned char*)v; }

    static int smem_set = 0;
    if (!smem_set) {
        cudaFuncSetAttribute(dynconv_tc, cudaFuncAttributeMaxDynamicSharedMemorySize,
                             DC_WORDS * 4);
        smem_set = 1;
    }

    const int MB = (MTOT + BM - 1) / BM;   // 19

    // 1. IoU + attention mask
    iou_mask_kernel<<<(Nb*NRr*NRr + 255)/256, 256>>>(bboxes, cm, p_mask);
    // 2. qk = pro + query
    add_kernel<<<(MTOT*Dd + 255)/256, 256>>>(pro, query, p_qk, MTOT*Dd);
    // 3-5. Q/K/V projections
    {
        dim3 g(Dd/BN, MB, 1);
        gemm_tc<<<g, 256>>>(p_qk, w_qkv,           b_qkv,        p_qp, MTOT, Dd, Dd, 0);
        gemm_tc<<<g, 256>>>(p_qk, w_qkv + Dd*Dd,   b_qkv + Dd,   p_kp, MTOT, Dd, Dd, 0);
        gemm_tc<<<g, 256>>>(pro,  w_qkv + 2*Dd*Dd, b_qkv + 2*Dd, p_vp, MTOT, Dd, Dd, 0);
    }
    // 6. masked MHSA
    attn_kernel<<<MTOT, 256>>>(p_qp, p_kp, p_vp, p_mask, p_ctx);
    // 7. out projection
    {
        dim3 g(Dd/BN, MB, 1);
        gemm_tc<<<g, 256>>>(p_ctx, w_ao, b_ao, p_t, MTOT, Dd, Dd, 0);
    }
    // 8. norm1 + mask
    ln_kernel<<<MTOT, 256>>>(p_t, pro, cm, p_pf1, 0);
    // 9. dynamic conv params GEMM [2400,32768] <- [2400,256] x [32768,256]^T
    {
        dim3 g(PAR/BN, MB, 1);
        gemm_tc<<<g, 256>>>(p_pf1, w_dyn, b_dyn, p_par, MTOT, PAR, Dd, 0);
    }
    // 10. per-instance dynamic conv (tensor cores)
    dynconv_tc<<<MTOT, 128, DC_WORDS*4>>>(roi, p_par, p_f2);
    // 11. dyn out projection, K=12544, split-K=8
    {
        dim3 g(Dd/BN, MB, 8);
        gemm_tc<<<g, 256>>>(p_f2, w_do, nullptr, p_part, MTOT, Dd, Ss*Dd, 0);
        reduce_splitk<<<(MTOT*Dd + 255)/256, 256>>>(p_part, b_do, p_t, 8, MTOT*Dd, Dd);
    }
    // 12. pf2 = relu(ln(t)); pfB = ln(pf1 + pf2)
    ln2_kernel<<<MTOT, 256>>>(p_t, p_pf1, p_pfB);
    // 13. FFN up + relu
    {
        dim3 g(FFf/BN, MB, 1);
        gemm_tc<<<g, 256>>>(p_pfB, w_ff1, b_ff1, p_ffh, MTOT, FFf, Dd, 1);
    }
    // 14. FFN down, K=2048, split-K=4
    {
        dim3 g(Dd/BN, MB, 4);
        gemm_tc<<<g, 256>>>(p_ffh, w_ff2, nullptr, p_part, MTOT, Dd, FFf, 0);
        reduce_splitk<<<(MTOT*Dd + 255)/256, 256>>>(p_part, b_ff2, p_t, 4, MTOT*Dd, Dd);
    }
    // 15. norm3 + mask
    ln_kernel<<<MTOT, 256>>>(p_t, p_pfB, cm, p_obj, 0);
    // 16. cls tower linear (bias-free)
    {
        dim3 g(Dd/BN, MB, 1);
        gemm_tc<<<g, 256>>>(p_obj, w_cls, nullptr, p_t, MTOT, Dd, Dd, 0);
    }
    // 17. relu(ln(.))
    ln_kernel<<<MTOT, 256>>>(p_t, nullptr, nullptr, p_clsf, 1);
    // 18. class logits (N=80)
    {
        dim3 g((NCc + BN - 1)/BN, MB, 1);
        gemm_tc<<<g, 256>>>(p_clsf, w_lg, b_lg, out, MTOT, NCc, Dd, 0);
    }
}

// round 3
// speedup vs baseline: 3.3355x; 1.2636x over previous
#include <cuda_runtime.h>
#include <math.h>

#define Nb   8
#define NRr  300
#define Dd   256
#define Hh   8
#define Ss   49
#define DDd  64
#define FFf  2048
#define NCc  80
#define MTOT (Nb*NRr)          // 2400
#define PAR  32768             // 2*D*DD

// ---------------- scratch (device globals; no allocation allowed) ----------------
__device__ float g_qk  [MTOT*Dd];
__device__ float g_qkp [MTOT*512];     // packed q|k projections
__device__ float g_vp  [MTOT*Dd];
__device__ float g_ctx [MTOT*Dd];
__device__ float g_t   [MTOT*Dd];
__device__ float g_pf1 [MTOT*Dd];
__device__ float g_pfB [MTOT*Dd];
__device__ float g_obj [MTOT*Dd];
__device__ float g_clsf[MTOT*Dd];
__device__ float g_ffh [MTOT*FFf];
__device__ float g_params[(size_t)MTOT*PAR];       // 314 MB
__device__ float g_f2  [(size_t)MTOT*Ss*Dd];       // 120 MB
__device__ float g_part[(size_t)8*MTOT*Dd];        // split-K partials
__device__ unsigned char g_maskb[Nb*NRr*NRr];

// ---------------- helpers ----------------
__device__ __forceinline__ unsigned f2tf(float x) {
    unsigned u;
    asm("cvt.rna.tf32.f32 %0, %1;" : "=r"(u) : "f"(x));
    return u;
}

__device__ __forceinline__ void mma_tf32(float* d, const unsigned* a, const unsigned* b) {
    asm volatile("mma.sync.aligned.m16n8k8.row.col.f32.tf32.tf32.f32 "
                 "{%0,%1,%2,%3}, {%4,%5,%6,%7}, {%8,%9}, {%0,%1,%2,%3};"
                 : "+f"(d[0]), "+f"(d[1]), "+f"(d[2]), "+f"(d[3])
                 : "r"(a[0]), "r"(a[1]), "r"(a[2]), "r"(a[3]), "r"(b[0]), "r"(b[1]));
}

__device__ __forceinline__ void cpa16(void* smem, const void* g, int sz) {
    unsigned d = (unsigned)__cvta_generic_to_shared(smem);
    asm volatile("cp.async.cg.shared.global [%0], [%1], 16, %2;" :: "r"(d), "l"(g), "r"(sz));
}

__device__ __forceinline__ float blockSum256(float v, float* red) {
#pragma unroll
    for (int o = 16; o; o >>= 1) v += __shfl_down_sync(0xffffffffu, v, o);
    if ((threadIdx.x & 31) == 0) red[threadIdx.x >> 5] = v;
    __syncthreads();
    float s = red[0]+red[1]+red[2]+red[3]+red[4]+red[5]+red[6]+red[7];
    __syncthreads();
    return s;
}

// ---------------- IoU + boolean attention mask ----------------
__global__ void iou_mask_kernel(const float* __restrict__ bb, const float* __restrict__ cm,
                                unsigned char* __restrict__ mask)
{
    int idx = blockIdx.x * blockDim.x + threadIdx.x;
    if (idx >= Nb*NRr*NRr) return;
    int b = idx / (NRr*NRr);
    int r = idx - b*NRr*NRr;
    int q = r / NRr, k = r - q*NRr;
    const float* bq = bb + (size_t)(b*NRr+q)*4;
    const float* bk = bb + (size_t)(b*NRr+k)*4;
    float areaA = (bq[2]-bq[0])*(bq[3]-bq[1]);
    float areaB = (bk[2]-bk[0])*(bk[3]-bk[1]);
    float ix = fmaxf(fminf(bq[2],bk[2]) - fmaxf(bq[0],bk[0]), 0.f);
    float iy = fmaxf(fminf(bq[3],bk[3]) - fmaxf(bq[1],bk[1]), 0.f);
    float inter = ix*iy;
    float iou = inter / fmaxf(areaA + areaB - inter, 1e-9f);
    float cq = cm[b*NRr+q], ck = cm[b*NRr+k];
    float omask = (iou < 0.5f) ? 1.f : 0.f;
    float val = omask*cq*ck + ((q==k) ? (1.f-cq) : 0.f);
    mask[idx] = (val > 0.f) ? (unsigned char)1 : (unsigned char)0;
}

// ---------------- elementwise add ----------------
__global__ void add_kernel(const float* __restrict__ a, const float* __restrict__ b,
                           float* __restrict__ o, int n)
{
    int i = blockIdx.x * blockDim.x + threadIdx.x;
    if (i < n) o[i] = a[i] + b[i];
}

// ================= tf32 tensor-core GEMM, cp.async double-buffered ==============
// C = A[M,K] @ W[N,K]^T (+bias)(opt relu)(opt split-K partials over gridDim.z).
// MT=2 -> BM=128 (warp tile 32x32), MT=1 -> BM=64 (warp tile 16x32). BN=64, BK=16.
// Smem layout [m][k] pitch 20 words -> conflict-free scalar fragment loads.
template<int MT>
__global__ void __launch_bounds__(256) gemm_tc(
    const float* __restrict__ A, const float* __restrict__ W,
    const float* __restrict__ bias, float* __restrict__ C,
    int M, int N, int K, int doRelu)
{
    constexpr int BMt = 64*MT;
    __shared__ unsigned As[2][BMt][20];
    __shared__ unsigned Bs[2][64][20];
    int tid  = threadIdx.x;
    int lane = tid & 31;
    int warp = tid >> 5;
    int rowBase = blockIdx.y * BMt;
    int colBase = blockIdx.x * 64;
    int kc   = K / gridDim.z;
    int kbeg = blockIdx.z * kc;
    float* Cp = C + (size_t)blockIdx.z * (size_t)M * (size_t)N;

    int mBase = (warp >> 1) * 16 * MT;
    int nBase = (warp & 1) * 32;
    int gr = lane >> 2, gc = lane & 3;

    float acc[MT][4][4];
#pragma unroll
    for (int a_ = 0; a_ < MT; ++a_)
#pragma unroll
        for (int b_ = 0; b_ < 4; ++b_)
#pragma unroll
            for (int c_ = 0; c_ < 4; ++c_) acc[a_][b_][c_] = 0.f;

    // staging thread mapping (16B units)
    int ar[MT], ak[MT];
#pragma unroll
    for (int c = 0; c < MT; ++c) { int u = tid + c*256; ar[c] = u >> 2; ak[c] = (u & 3) * 4; }
    int br = tid >> 2, bk = (tid & 3) * 4;

    int nIter = kc / 16;

    // prefetch iter 0
    {
#pragma unroll
        for (int c = 0; c < MT; ++c) {
            int r = rowBase + ar[c];
            int rc = (r < M) ? r : (M - 1);
            cpa16(&As[0][ar[c]][ak[c]], A + (size_t)rc*K + kbeg + ak[c], (r < M) ? 16 : 0);
        }
        int n = colBase + br;
        int ncl = (n < N) ? n : (N - 1);
        cpa16(&Bs[0][br][bk], W + (size_t)ncl*K + kbeg + bk, (n < N) ? 16 : 0);
        asm volatile("cp.async.commit_group;");
    }

    for (int i = 0; i < nIter; ++i) {
        if (i + 1 < nIter) {
            int k0 = kbeg + (i+1)*16;
            int nb = (i+1) & 1;
#pragma unroll
            for (int c = 0; c < MT; ++c) {
                int r = rowBase + ar[c];
                int rc = (r < M) ? r : (M - 1);
                cpa16(&As[nb][ar[c]][ak[c]], A + (size_t)rc*K + k0 + ak[c], (r < M) ? 16 : 0);
            }
            int n = colBase + br;
            int ncl = (n < N) ? n : (N - 1);
            cpa16(&Bs[nb][br][bk], W + (size_t)ncl*K + k0 + bk, (n < N) ? 16 : 0);
            asm volatile("cp.async.commit_group;");
            asm volatile("cp.async.wait_group 1;");
        } else {
            asm volatile("cp.async.wait_group 0;");
        }
        __syncthreads();
        int buf = i & 1;
#pragma unroll
        for (int ks = 0; ks < 16; ks += 8) {
            unsigned a[MT][4], b[4][2];
#pragma unroll
            for (int mt = 0; mt < MT; ++mt) {
                int row = mBase + mt*16;
                a[mt][0] = f2tf(__uint_as_float(As[buf][row+gr  ][ks+gc  ]));
                a[mt][1] = f2tf(__uint_as_float(As[buf][row+gr+8][ks+gc  ]));
                a[mt][2] = f2tf(__uint_as_float(As[buf][row+gr  ][ks+4+gc]));
                a[mt][3] = f2tf(__uint_as_float(As[buf][row+gr+8][ks+4+gc]));
            }
#pragma unroll
            for (int nt = 0; nt < 4; ++nt) {
                int col = nBase + nt*8;
                b[nt][0] = f2tf(__uint_as_float(Bs[buf][col+gr][ks+gc  ]));
                b[nt][1] = f2tf(__uint_as_float(Bs[buf][col+gr][ks+4+gc]));
            }
#pragma unroll
            for (int mt = 0; mt < MT; ++mt)
#pragma unroll
                for (int nt = 0; nt < 4; ++nt)
                    mma_tf32(acc[mt][nt], a[mt], b[nt]);
        }
        __syncthreads();
    }

    // epilogue: paired float2 stores
#pragma unroll
    for (int mt = 0; mt < MT; ++mt) {
#pragma unroll
        for (int nt = 0; nt < 4; ++nt) {
            int c = colBase + nBase + nt*8 + gc*2;
            if (c >= N) continue;
            float bx = bias ? bias[c]   : 0.f;
            float by = bias ? bias[c+1] : 0.f;
            int r0 = rowBase + mBase + mt*16 + gr;
            if (r0 < M) {
                float x = acc[mt][nt][0] + bx, y = acc[mt][nt][1] + by;
                if (doRelu) { x = fmaxf(x,0.f); y = fmaxf(y,0.f); }
                *(float2*)(Cp + (size_t)r0*N + c) = make_float2(x, y);
            }
            int r1 = r0 + 8;
            if (r1 < M) {
                float x = acc[mt][nt][2] + bx, y = acc[mt][nt][3] + by;
                if (doRelu) { x = fmaxf(x,0.f); y = fmaxf(y,0.f); }
                *(float2*)(Cp + (size_t)r1*N + c) = make_float2(x, y);
            }
        }
    }
}

// ---------------- split-K reduce ----------------
__global__ void reduce_splitk(const float* __restrict__ part, const float* __restrict__ bias,
                              float* __restrict__ out, int nz, int MN, int Ncol)
{
    int i = blockIdx.x * blockDim.x + threadIdx.x;
    if (i >= MN) return;
    float s = 0.f;
    for (int z = 0; z < nz; ++z) s += part[(size_t)z*MN + i];
    if (bias) s += bias[i % Ncol];
    out[i] = s;
}

// ---------------- masked multi-head attention (q|k packed stride 512) -----------
__global__ void attn_kernel(const float* __restrict__ qkp, const float* __restrict__ vp,
                            const unsigned char* __restrict__ mask, float* __restrict__ ctx)
{
    __shared__ float sc[Hh][NRr];
    __shared__ float sq[Hh][32];
    int bq = blockIdx.x;
    int b = bq / NRr, q = bq - b*NRr;
    int w = threadIdx.x >> 5;
    int lane = threadIdx.x & 31;

    sq[w][lane] = qkp[(size_t)bq*512 + w*32 + lane];
    __syncwarp();

    const unsigned char* mrow = mask + (size_t)b*NRr*NRr + (size_t)q*NRr;
    const float scale = 0.17677669529663687f;   // 1/sqrt(32)

    for (int k = lane; k < NRr; k += 32) {
        const float4* kr = (const float4*)(qkp + ((size_t)(b*NRr + k))*512 + 256 + w*32);
        float s = 0.f;
#pragma unroll
        for (int u = 0; u < 8; ++u) {
            float4 kv = kr[u];
            s += sq[w][u*4+0]*kv.x + sq[w][u*4+1]*kv.y + sq[w][u*4+2]*kv.z + sq[w][u*4+3]*kv.w;
        }
        s *= scale;
        if (mrow[k]) s = -1e9f;
        sc[w][k] = s;
    }
    __syncwarp();
    float mx = -1e30f;
    for (int k = lane; k < NRr; k += 32) mx = fmaxf(mx, sc[w][k]);
#pragma unroll
    for (int o = 16; o; o >>= 1) mx = fmaxf(mx, __shfl_xor_sync(0xffffffffu, mx, o));
    float sum = 0.f;
    for (int k = lane; k < NRr; k += 32) { float e = expf(sc[w][k]-mx); sc[w][k] = e; sum += e; }
#pragma unroll
    for (int o = 16; o; o >>= 1) sum += __shfl_xor_sync(0xffffffffu, sum, o);
    __syncwarp();
    float inv = 1.f / sum;

    float acc = 0.f;
#pragma unroll 4
    for (int k = 0; k < NRr; ++k)
        acc += sc[w][k] * vp[((size_t)(b*NRr + k))*Dd + w*32 + lane];
    ctx[(size_t)bq*Dd + w*32 + lane] = acc * inv;
}

// ---------------- LayerNorm row kernel (D=256) ----------------
__global__ void ln_kernel(const float* __restrict__ X, const float* __restrict__ R,
                          const float* __restrict__ mrow, float* __restrict__ out, int doRelu)
{
    __shared__ float red[8];
    int i = blockIdx.x, t = threadIdx.x;
    float x = X[(size_t)i*Dd + t];
    if (R) x += R[(size_t)i*Dd + t];
    float m  = blockSum256(x, red) * (1.f/Dd);
    float dv = x - m;
    float var = blockSum256(dv*dv, red) * (1.f/Dd);
    float y = dv * rsqrtf(var + 1e-5f);
    if (doRelu) y = fmaxf(y, 0.f);
    if (mrow) y *= mrow[i];
    out[(size_t)i*Dd + t] = y;
}

// ---------------- double LN: out = ln( relu(ln(X)) + P ) -------------------------
__global__ void ln2_kernel(const float* __restrict__ X, const float* __restrict__ P,
                           float* __restrict__ out)
{
    __shared__ float red[8];
    int i = blockIdx.x, t = threadIdx.x;
    float x = X[(size_t)i*Dd + t];
    float m  = blockSum256(x, red) * (1.f/Dd);
    float dv = x - m;
    float var = blockSum256(dv*dv, red) * (1.f/Dd);
    float y = fmaxf(dv * rsqrtf(var + 1e-5f), 0.f);
    float z = y + P[(size_t)i*Dd + t];
    m  = blockSum256(z, red) * (1.f/Dd);
    dv = z - m;
    var = blockSum256(dv*dv, red) * (1.f/Dd);
    out[(size_t)i*Dd + t] = dv * rsqrtf(var + 1e-5f);
}

// ================= DynamicConv on tensor cores ===================================
#define DC_AS   0
#define DC_BS   (32*72)
#define DC_F1   (DC_BS + 32*72)
#define DC_BS2  (DC_F1 + 64*72)
#define DC_F2R  (DC_BS2 + 64*72)
#define DC_WORDS (DC_F2R + 49*264)     // 26760 words = 107040 bytes

__global__ void __launch_bounds__(128) dynconv_tc(
    const float* __restrict__ roi, const float* __restrict__ params,
    float* __restrict__ f2out)
{
    extern __shared__ unsigned sm[];
    unsigned* Asm = sm + DC_AS;     // [k=32][s=64] pitch 72
    unsigned* Bsm = sm + DC_BS;     // [k=32][e=64] pitch 72
    unsigned* f1t = sm + DC_F1;     // [e=64][s=64] pitch 72
    unsigned* Bs2 = sm + DC_BS2;    // [e=64][n=64] pitch 72
    float*    f2r = (float*)(sm + DC_F2R);  // [s=49][d=256] pitch 264

    int i    = blockIdx.x;
    int tid  = threadIdx.x;
    int lane = tid & 31;
    int warp = tid >> 5;
    int gr = lane >> 2, gc = lane & 3;
    int rowW = warp * 16;

    const float* p1 = params + (size_t)i * PAR;
    const float* p2 = p1 + Dd*DDd;

    // ---------------- Step 1 ----------------
    float acc1[8][4];
#pragma unroll
    for (int a_ = 0; a_ < 8; ++a_)
#pragma unroll
        for (int c_ = 0; c_ < 4; ++c_) acc1[a_][c_] = 0.f;

    for (int dc = 0; dc < Dd; dc += 32) {
        __syncthreads();
#pragma unroll
        for (int p = 0; p < 4; ++p) {
            int s  = p*16 + (tid >> 3);
            int d4 = (tid & 7) * 4;
            float4 v = make_float4(0.f,0.f,0.f,0.f);
            if (s < Ss) v = *(const float4*)(roi + ((size_t)s*MTOT + i)*Dd + dc + d4);
            Asm[(d4+0)*72 + s] = f2tf(v.x);
            Asm[(d4+1)*72 + s] = f2tf(v.y);
            Asm[(d4+2)*72 + s] = f2tf(v.z);
            Asm[(d4+3)*72 + s] = f2tf(v.w);
        }
#pragma unroll
        for (int p = 0; p < 4; ++p) {
            int d  = p*8 + (tid >> 4);
            int e4 = (tid & 15) * 4;
            float4 v = *(const float4*)(p1 + (size_t)(dc + d)*DDd + e4);
            Bsm[d*72 + e4+0] = f2tf(v.x);
            Bsm[d*72 + e4+1] = f2tf(v.y);
            Bsm[d*72 + e4+2] = f2tf(v.z);
            Bsm[d*72 + e4+3] = f2tf(v.w);
        }
        __syncthreads();
#pragma unroll
        for (int ks = 0; ks < 32; ks += 8) {
            unsigned a[4], b[8][2];
            a[0] = Asm[(ks+gc  )*72 + rowW+gr  ];
            a[1] = Asm[(ks+gc  )*72 + rowW+gr+8];
            a[2] = Asm[(ks+4+gc)*72 + rowW+gr  ];
            a[3] = Asm[(ks+4+gc)*72 + rowW+gr+8];
#pragma unroll
            for (int nt = 0; nt < 8; ++nt) {
                b[nt][0] = Bsm[(ks+gc  )*72 + nt*8+gr];
                b[nt][1] = Bsm[(ks+4+gc)*72 + nt*8+gr];
            }
#pragma unroll
            for (int nt = 0; nt < 8; ++nt) mma_tf32(acc1[nt], a, b[nt]);
        }
    }
    {
        float s0 = 0.f, s1 = 0.f;
#pragma unroll
        for (int nt = 0; nt < 8; ++nt) { s0 += acc1[nt][0]+acc1[nt][1]; s1 += acc1[nt][2]+acc1[nt][3]; }
        s0 += __shfl_xor_sync(0xffffffffu, s0, 1); s0 += __shfl_xor_sync(0xffffffffu, s0, 2);
        s1 += __shfl_xor_sync(0xffffffffu, s1, 1); s1 += __shfl_xor_sync(0xffffffffu, s1, 2);
        float m0 = s0 * (1.f/DDd), m1 = s1 * (1.f/DDd);
        float v0 = 0.f, v1 = 0.f;
#pragma unroll
        for (int nt = 0; nt < 8; ++nt) {
            float d0 = acc1[nt][0]-m0, d1 = acc1[nt][1]-m0;
            float d2 = acc1[nt][2]-m1, d3 = acc1[nt][3]-m1;
            v0 += d0*d0 + d1*d1; v1 += d2*d2 + d3*d3;
        }
        v0 += __shfl_xor_sync(0xffffffffu, v0, 1); v0 += __shfl_xor_sync(0xffffffffu, v0, 2);
        v1 += __shfl_xor_sync(0xffffffffu, v1, 1); v1 += __shfl_xor_sync(0xffffffffu, v1, 2);
        float r0f = rsqrtf(v0*(1.f/DDd) + 1e-5f);
        float r1f = rsqrtf(v1*(1.f/DDd) + 1e-5f);
        int sr0 = rowW + gr, sr1 = sr0 + 8;
#pragma unroll
        for (int nt = 0; nt < 8; ++nt) {
            int e = nt*8 + gc*2;
            f1t[(e  )*72 + sr0] = f2tf(fmaxf((acc1[nt][0]-m0)*r0f, 0.f));
            f1t[(e+1)*72 + sr0] = f2tf(fmaxf((acc1[nt][1]-m0)*r0f, 0.f));
            f1t[(e  )*72 + sr1] = f2tf(fmaxf((acc1[nt][2]-m1)*r1f, 0.f));
            f1t[(e+1)*72 + sr1] = f2tf(fmaxf((acc1[nt][3]-m1)*r1f, 0.f));
        }
    }

    // ---------------- Step 2 ----------------
    for (int nc = 0; nc < Dd; nc += 64) {
        __syncthreads();
#pragma unroll
        for (int p = 0; p < 8; ++p) {
            int e  = p*8 + (tid >> 4);
            int n4 = (tid & 15) * 4;
            float4 v = *(const float4*)(p2 + (size_t)e*Dd + nc + n4);
            Bs2[e*72 + n4+0] = f2tf(v.x);
            Bs2[e*72 + n4+1] = f2tf(v.y);
            Bs2[e*72 + n4+2] = f2tf(v.z);
            Bs2[e*72 + n4+3] = f2tf(v.w);
        }
        __syncthreads();
        float acc2[8][4];
#pragma unroll
        for (int a_ = 0; a_ < 8; ++a_)
#pragma unroll
            for (int c_ = 0; c_ < 4; ++c_) acc2[a_][c_] = 0.f;
#pragma unroll
        for (int ks = 0; ks < 64; ks += 8) {
            unsigned a[4], b[8][2];
            a[0] = f1t[(ks+gc  )*72 + rowW+gr  ];
            a[1] = f1t[(ks+gc  )*72 + rowW+gr+8];
            a[2] = f1t[(ks+4+gc)*72 + rowW+gr  ];
            a[3] = f1t[(ks+4+gc)*72 + rowW+gr+8];
#pragma unroll
            for (int nt = 0; nt < 8; ++nt) {
                b[nt][0] = Bs2[(ks+gc  )*72 + nt*8+gr];
                b[nt][1] = Bs2[(ks+4+gc)*72 + nt*8+gr];
            }
#pragma unroll
            for (int nt = 0; nt < 8; ++nt) mma_tf32(acc2[nt], a, b[nt]);
        }
        int sr0 = rowW + gr, sr1 = sr0 + 8;
#pragma unroll
        for (int nt = 0; nt < 8; ++nt) {
            int c = nc + nt*8 + gc*2;
            if (sr0 < Ss) *(float2*)(f2r + sr0*264 + c) = make_float2(acc2[nt][0], acc2[nt][1]);
            if (sr1 < Ss) *(float2*)(f2r + sr1*264 + c) = make_float2(acc2[nt][2], acc2[nt][3]);
        }
    }
    __syncthreads();

    for (int s = warp; s < Ss; s += 4) {
        float v[8];
        float sum = 0.f;
#pragma unroll
        for (int j = 0; j < 8; ++j) { v[j] = f2r[s*264 + lane + 32*j]; sum += v[j]; }
#pragma unroll
        for (int o = 16; o; o >>= 1) sum += __shfl_xor_sync(0xffffffffu, sum, o);
        float m = sum * (1.f/Dd);
        float var = 0.f;
#pragma unroll
        for (int j = 0; j < 8; ++j) { float d = v[j]-m; var += d*d; }
#pragma unroll
        for (int o = 16; o; o >>= 1) var += __shfl_xor_sync(0xffffffffu, var, o);
        float rs = rsqrtf(var*(1.f/Dd) + 1e-5f);
        float* op = f2out + ((size_t)i*Ss + s)*Dd;
#pragma unroll
        for (int j = 0; j < 8; ++j)
            op[lane + 32*j] = fmaxf((v[j]-m)*rs, 0.f);
    }
}

// ---------------- host side ----------------
static float* symaddr(const void* sym) { void* p = nullptr; cudaGetSymbolAddress(&p, sym); return (float*)p; }

extern "C" void kernel_launch(void* const* d_in, const int* in_sizes, int n_in,
                              void* d_out, int out_size)
{
    const float* bboxes = (const float*)d_in[0];
    const float* pro    = (const float*)d_in[1];
    const float* roi    = (const float*)d_in[2];
    const float* query  = (const float*)d_in[3];
    const float* cm     = (const float*)d_in[4];
    const float* w_qkv  = (const float*)d_in[5];
    const float* b_qkv  = (const float*)d_in[6];
    const float* w_ao   = (const float*)d_in[7];
    const float* b_ao   = (const float*)d_in[8];
    const float* w_dyn  = (const float*)d_in[9];
    const float* b_dyn  = (const float*)d_in[10];
    const float* w_do   = (const float*)d_in[11];
    const float* b_do   = (const float*)d_in[12];
    const float* w_ff1  = (const float*)d_in[13];
    const float* b_ff1  = (const float*)d_in[14];
    const float* w_ff2  = (const float*)d_in[15];
    const float* b_ff2  = (const float*)d_in[16];
    const float* w_cls  = (const float*)d_in[17];
    const float* w_lg   = (const float*)d_in[18];
    const float* b_lg   = (const float*)d_in[19];
    float* out = (float*)d_out;

    float* p_qk   = symaddr(g_qk);
    float* p_qkp  = symaddr(g_qkp);
    float* p_vp   = symaddr(g_vp);
    float* p_ctx  = symaddr(g_ctx);
    float* p_t    = symaddr(g_t);
    float* p_pf1  = symaddr(g_pf1);
    float* p_pfB  = symaddr(g_pfB);
    float* p_obj  = symaddr(g_obj);
    float* p_clsf = symaddr(g_clsf);
    float* p_ffh  = symaddr(g_ffh);
    float* p_par  = symaddr(g_params);
    float* p_f2   = symaddr(g_f2);
    float* p_part = symaddr(g_part);
    unsigned char* p_mask; { void* v; cudaGetSymbolAddress(&v, g_maskb); p_mask = (unsigned char*)v; }

    static int smem_set = 0;
    if (!smem_set) {
        cudaFuncSetAttribute(dynconv_tc, cudaFuncAttributeMaxDynamicSharedMemorySize,
                             DC_WORDS * 4);
        smem_set = 1;
    }

    const int MB128 = (MTOT + 127) / 128;   // 19
    const int MB64  = (MTOT + 63) / 64;     // 38

    // 1. IoU + attention mask
    iou_mask_kernel<<<(Nb*NRr*NRr + 255)/256, 256>>>(bboxes, cm, p_mask);
    // 2. qk = pro + query
    add_kernel<<<(MTOT*Dd + 255)/256, 256>>>(pro, query, p_qk, MTOT*Dd);
    // 3. merged Q|K projection (N=512) and V projection
    gemm_tc<1><<<dim3(512/64, MB64, 1), 256>>>(p_qk, w_qkv,           b_qkv,        p_qkp, MTOT, 512, Dd, 0);
    gemm_tc<1><<<dim3(Dd/64,  MB64, 1), 256>>>(pro,  w_qkv + 2*Dd*Dd, b_qkv + 2*Dd, p_vp,  MTOT, Dd,  Dd, 0);
    // 4. masked MHSA
    attn_kernel<<<MTOT, 256>>>(p_qkp, p_vp, p_mask, p_ctx);
    // 5. out projection
    gemm_tc<1><<<dim3(Dd/64, MB64, 1), 256>>>(p_ctx, w_ao, b_ao, p_t, MTOT, Dd, Dd, 0);
    // 6. norm1 + mask
    ln_kernel<<<MTOT, 256>>>(p_t, pro, cm, p_pf1, 0);
    // 7. dynamic conv params GEMM [2400,32768]
    gemm_tc<2><<<dim3(PAR/64, MB128, 1), 256>>>(p_pf1, w_dyn, b_dyn, p_par, MTOT, PAR, Dd, 0);
    // 8. per-instance dynamic conv
    dynconv_tc<<<MTOT, 128, DC_WORDS*4>>>(roi, p_par, p_f2);
    // 9. dyn out projection, K=12544, split-K=8
    gemm_tc<2><<<dim3(Dd/64, MB128, 8), 256>>>(p_f2, w_do, nullptr, p_part, MTOT, Dd, Ss*Dd, 0);
    reduce_splitk<<<(MTOT*Dd + 255)/256, 256>>>(p_part, b_do, p_t, 8, MTOT*Dd, Dd);
    // 10. pf2 = relu(ln(t)); pfB = ln(pf1 + pf2)
    ln2_kernel<<<MTOT, 256>>>(p_t, p_pf1, p_pfB);
    // 11. FFN up + relu
    gemm_tc<2><<<dim3(FFf/64, MB128, 1), 256>>>(p_pfB, w_ff1, b_ff1, p_ffh, MTOT, FFf, Dd, 1);
    // 12. FFN down, K=2048, split-K=4
    gemm_tc<2><<<dim3(Dd/64, MB128, 4), 256>>>(p_ffh, w_ff2, nullptr, p_part, MTOT, Dd, FFf, 0);
    reduce_splitk<<<(MTOT*Dd + 255)/256, 256>>>(p_part, b_ff2, p_t, 4, MTOT*Dd, Dd);
    // 13. norm3 + mask
    ln_kernel<<<MTOT, 256>>>(p_t, p_pfB, cm, p_obj, 0);
    // 14. cls tower linear (bias-free)
    gemm_tc<1><<<dim3(Dd/64, MB64, 1), 256>>>(p_obj, w_cls, nullptr, p_t, MTOT, Dd, Dd, 0);
    // 15. relu(ln(.))
    ln_kernel<<<MTOT, 256>>>(p_t, nullptr, nullptr, p_clsf, 1);
    // 16. class logits (N=80)
    gemm_tc<1><<<dim3((NCc + 63)/64, MB64, 1), 256>>>(p_clsf, w_lg, b_lg, out, MTOT, NCc, Dd, 0);
}